// round 13
// baseline (speedup 1.0000x reference)
#include <cuda_runtime.h>
#include <cuda_bf16.h>
#include <mma.h>
#include <math.h>

using namespace nvcuda;

#define NB      65536
#define DIM     256
#define BANK_N  1000
#define BANK_P  1024
#define CUTW    1.5e-3f

typedef unsigned int       u32;
typedef __nv_bfloat16      bf16;

// ---------------- device scratch (static) ----------------
__device__ __align__(16) bf16  g_bn0[BANK_P * DIM];
__device__ __align__(16) bf16  g_qn0[(size_t)NB * DIM];
__device__ __align__(16) float g_binv[BANK_P];
__device__ __align__(16) float g_qinv[NB];
__device__ __align__(16) float g_sims[(size_t)NB * BANK_P];   // 268 MB
__device__ __align__(16) bf16  g_f0[(size_t)NB * DIM];
__device__ __align__(16) bf16  g_f1[(size_t)NB * DIM];
__device__ __align__(16) bf16  g_nf0[(size_t)NB * DIM];
__device__ __align__(16) bf16  g_nf1[(size_t)NB * DIM];
__device__ __align__(16) bf16  g_h0[(size_t)NB * DIM];
__device__ __align__(16) bf16  g_h1[(size_t)NB * DIM];
__device__ __align__(16) bf16  g_w10[DIM * 2 * DIM];
__device__ __align__(16) bf16  g_w11[DIM * 2 * DIM];
__device__ __align__(16) bf16  g_w20[DIM * DIM];
__device__ __align__(16) bf16  g_w21[DIM * DIM];

// ---------------- helpers ----------------
__device__ __forceinline__ u32 smem_u32(const void* p) {
    u32 a;
    asm("{ .reg .u64 t; cvta.to.shared.u64 t, %1; cvt.u32.u64 %0, t; }" : "=r"(a) : "l"(p));
    return a;
}
__device__ __forceinline__ void cp16(u32 dst, const void* src) {
    asm volatile("cp.async.cg.shared.global [%0], [%1], 16;" :: "r"(dst), "l"(src));
}
__device__ __forceinline__ void cp_commit() { asm volatile("cp.async.commit_group;" ::: "memory"); }
__device__ __forceinline__ void cp_wait0()  { asm volatile("cp.async.wait_group 0;" ::: "memory"); }
__device__ __forceinline__ void cp_wait1()  { asm volatile("cp.async.wait_group 1;" ::: "memory"); }

__device__ __forceinline__ u32 redux_max_u32(u32 v) {
    u32 r;
    asm("redux.sync.max.u32 %0, %1, 0xffffffff;" : "=r"(r) : "r"(v));
    return r;
}
__device__ __forceinline__ u32 redux_min_u32(u32 v) {
    u32 r;
    asm("redux.sync.min.u32 %0, %1, 0xffffffff;" : "=r"(r) : "r"(v));
    return r;
}
// order-preserving f32 <-> u32 transforms
__device__ __forceinline__ u32 ford(float f) {
    u32 u = __float_as_uint(f);
    return (u & 0x80000000u) ? ~u : (u | 0x80000000u);
}
__device__ __forceinline__ float funord(u32 k) {
    u32 u = (k & 0x80000000u) ? (k ^ 0x80000000u) : ~k;
    return __uint_as_float(u);
}

typedef wmma::fragment<wmma::matrix_a, 16, 16, 16, bf16, wmma::row_major> FragA;
typedef wmma::fragment<wmma::matrix_b, 16, 16, 16, bf16, wmma::col_major> FragB;
typedef wmma::fragment<wmma::accumulator, 16, 16, 16, float> FragC;

__device__ __forceinline__ float warp_row_sumsq(float4 v0, float4 v1) {
    float s = v0.x*v0.x + v0.y*v0.y + v0.z*v0.z + v0.w*v0.w
            + v1.x*v1.x + v1.y*v1.y + v1.z*v1.z + v1.w*v1.w;
    #pragma unroll
    for (int o = 16; o; o >>= 1) s += __shfl_xor_sync(0xffffffffu, s, o);
    return s;
}
__device__ __forceinline__ void split2(float x, bf16& a, bf16& b) {
    a = __float2bfloat16(x);
    b = __float2bfloat16(x - __bfloat162float(a));
}

// ---------------- split kernels ----------------
__global__ void k_bank_split(const float* __restrict__ bank) {
    const int w = threadIdx.x >> 5, l = threadIdx.x & 31;
    const int r = blockIdx.x * 8 + w;
    float4 v0 = make_float4(0,0,0,0), v1 = v0;
    if (r < BANK_N) {
        const float* src = bank + (size_t)r * DIM + l * 8;
        v0 = *(const float4*)src; v1 = *(const float4*)(src + 4);
    }
    const float s = warp_row_sumsq(v0, v1);
    const float inv = 1.0f / fmaxf(sqrtf(s), 1e-12f);
    float xv[8] = {v0.x, v0.y, v0.z, v0.w, v1.x, v1.y, v1.z, v1.w};
    bf16 o0[8];
    #pragma unroll
    for (int i = 0; i < 8; i++)
        o0[i] = __float2bfloat16((r < BANK_N) ? xv[i] * inv : 0.0f);
    *(uint4*)(g_bn0 + (size_t)r * DIM + l * 8) = *(uint4*)o0;
    if (l == 0) g_binv[r] = (r < BANK_N) ? inv : 0.0f;
}

__global__ void k_feat_split(const float* __restrict__ feat) {
    const int w = threadIdx.x >> 5, l = threadIdx.x & 31;
    const int r = blockIdx.x * 8 + w;
    const float* src = feat + (size_t)r * DIM + l * 8;
    float4 v0 = *(const float4*)src;
    float4 v1 = *(const float4*)(src + 4);
    const float s = warp_row_sumsq(v0, v1);
    const float inv = 1.0f / fmaxf(sqrtf(s), 1e-12f);
    float xv[8] = {v0.x, v0.y, v0.z, v0.w, v1.x, v1.y, v1.z, v1.w};
    bf16 q0[8], f0[8], f1[8];
    #pragma unroll
    for (int i = 0; i < 8; i++) {
        q0[i] = __float2bfloat16(xv[i] * inv);
        split2(xv[i], f0[i], f1[i]);
    }
    const size_t o = (size_t)r * DIM + l * 8;
    *(uint4*)(g_qn0 + o) = *(uint4*)q0;
    *(uint4*)(g_f0 + o)  = *(uint4*)f0;
    *(uint4*)(g_f1 + o)  = *(uint4*)f1;
    if (l == 0) g_qinv[r] = inv;
}

__global__ void k_w_split(const float* __restrict__ W1, const float* __restrict__ W2) {
    const int i = blockIdx.x * 256 + threadIdx.x;
    if (i < DIM * 2 * DIM) split2(W1[i], g_w10[i], g_w11[i]);
    if (i < DIM * DIM)     split2(W2[i], g_w20[i], g_w21[i]);
}

// ---------------- k_sims_gemm: pure bf16 GEMM -> g_sims (fp32, direct frag stores) ----------------
// smem: As @0 (64x264 bf16 = 33792) ; Bbuf @33792 2 x (256x72 bf16 = 36864)
#define S_AS 0
#define S_BB 33792
#define SIMS_SMEM 107520

__global__ __launch_bounds__(256, 2) void k_sims_gemm() {
    extern __shared__ char sm[];
    bf16* As = (bf16*)(sm + S_AS);
    const u32 sb = smem_u32(sm);
    const int t = threadIdx.x, w = t >> 5;
    const int wy = w >> 2, wx = w & 3;          // 2x4 warps -> CTA tile 64 x 256
    const int q0 = blockIdx.x * 64;

    // prologue: stage B(nt0,kt0) into buf0 (async), then A resident
    #pragma unroll
    for (int i = t; i < 2048; i += 256) {
        const int c = i >> 3, seg = i & 7;
        cp16(sb + S_BB + c * 144 + seg * 16, g_bn0 + (size_t)c * DIM + seg * 8);
    }
    cp_commit();
    #pragma unroll
    for (int i = t; i < 2048; i += 256) {
        const int row = i >> 5, seg = i & 31;
        *(uint4*)(As + row * 264 + seg * 8) =
            *(const uint4*)(g_qn0 + (size_t)(q0 + row) * DIM + seg * 8);
    }

    #pragma unroll 1
    for (int nt = 0; nt < 4; nt++) {
        FragC c[2][4];
        #pragma unroll
        for (int i = 0; i < 2; i++)
            #pragma unroll
            for (int j = 0; j < 4; j++) wmma::fill_fragment(c[i][j], 0.0f);

        #pragma unroll 1
        for (int kt = 0; kt < 4; kt++) {
            const int buf = kt & 1;
            if (kt < 3) {
                const u32 db = sb + S_BB + (buf ^ 1) * 36864;
                #pragma unroll
                for (int i = t; i < 2048; i += 256) {
                    const int cc = i >> 3, seg = i & 7;
                    cp16(db + cc * 144 + seg * 16,
                         g_bn0 + (size_t)(nt * 256 + cc) * DIM + (kt + 1) * 64 + seg * 8);
                }
                cp_commit();
                cp_wait1();
            } else {
                cp_wait0();
            }
            __syncthreads();

            const bf16* Bb = (const bf16*)(sm + S_BB + buf * 36864);
            #pragma unroll
            for (int kk = 0; kk < 4; kk++) {
                FragA a[2];
                #pragma unroll
                for (int i = 0; i < 2; i++)
                    wmma::load_matrix_sync(a[i],
                        As + (wy * 32 + i * 16) * 264 + kt * 64 + kk * 16, 264);
                #pragma unroll
                for (int j = 0; j < 4; j++) {
                    FragB b;
                    wmma::load_matrix_sync(b, Bb + (wx * 64 + j * 16) * 72 + kk * 16, 72);
                    wmma::mma_sync(c[0][j], a[0], b, c[0][j]);
                    wmma::mma_sync(c[1][j], a[1], b, c[1][j]);
                }
            }
            __syncthreads();
        }

        // overlap: prestage next chunk's kt0 into buf0 (buf0 idle since kt=2 sync)
        if (nt < 3) {
            #pragma unroll
            for (int i = t; i < 2048; i += 256) {
                const int cc = i >> 3, seg = i & 7;
                cp16(sb + S_BB + cc * 144 + seg * 16,
                     g_bn0 + (size_t)((nt + 1) * 256 + cc) * DIM + seg * 8);
            }
            cp_commit();
        }

        // store fragments straight to global sims
        #pragma unroll
        for (int i = 0; i < 2; i++)
            #pragma unroll
            for (int j = 0; j < 4; j++)
                wmma::store_matrix_sync(
                    g_sims + (size_t)(q0 + wy * 32 + i * 16) * BANK_P + nt * 256 + wx * 64 + j * 16,
                    c[i][j], BANK_P, wmma::mem_row_major);
    }
}

// ---------------- k_select: warp per row; redux merge + exact refine + gather ----------------
__global__ __launch_bounds__(256) void k_select(const float* __restrict__ feat,
                                               const float* __restrict__ bank) {
    const int t = threadIdx.x, wid = t >> 5, lane = t & 31;
    const int r = blockIdx.x * 8 + wid;

    // exact qn slice for this lane (dims lane*8 .. lane*8+7)
    const float qinv = g_qinv[r];
    float qn[8];
    {
        const float4* fp = (const float4*)(feat + (size_t)r * DIM + lane * 8);
        float4 a = __ldg(fp), b = __ldg(fp + 1);
        qn[0] = a.x * qinv; qn[1] = a.y * qinv; qn[2] = a.z * qinv; qn[3] = a.w * qinv;
        qn[4] = b.x * qinv; qn[5] = b.y * qinv; qn[6] = b.z * qinv; qn[7] = b.w * qinv;
    }

    // lane-local top-5 over 32 coalesced values
    float tv[5]; int ti[5];
    #pragma unroll
    for (int i = 0; i < 5; i++) { tv[i] = -3e38f; ti[i] = 0x7fffffff; }
    const float* srow = g_sims + (size_t)r * BANK_P;
    #pragma unroll 4
    for (int j = 0; j < 32; j++) {
        const int idx = j * 32 + lane;
        float s = __ldg(srow + idx);
        if (idx >= BANK_N) s = -3e38f;
        if (s > tv[4]) {
            tv[4] = s; ti[4] = idx;
            if (tv[4] > tv[3]) { float a=tv[4];tv[4]=tv[3];tv[3]=a; int b=ti[4];ti[4]=ti[3];ti[3]=b; }
            if (tv[3] > tv[2]) { float a=tv[3];tv[3]=tv[2];tv[2]=a; int b=ti[3];ti[3]=ti[2];ti[2]=b; }
            if (tv[2] > tv[1]) { float a=tv[2];tv[2]=tv[1];tv[1]=a; int b=ti[2];ti[2]=ti[1];ti[1]=b; }
            if (tv[1] > tv[0]) { float a=tv[1];tv[1]=tv[0];tv[0]=a; int b=ti[1];ti[1]=ti[0];ti[0]=b; }
        }
    }

    // warp merge via redux: extract row top-12 (descending, tie -> lower idx)
    float wv[12]; int wix[12];
    #pragma unroll
    for (int k = 0; k < 12; k++) {
        const u32 key = ford(tv[0]);
        const u32 mx = redux_max_u32(key);
        const bool has = (key == mx);
        const u32 cand = has ? (u32)ti[0] : 0xffffffffu;
        const u32 mi = redux_min_u32(cand);
        wv[k] = funord(mx);
        wix[k] = (int)mi;
        if (has && (u32)ti[0] == mi) {   // winner lane: shift list down
            tv[0]=tv[1]; ti[0]=ti[1];
            tv[1]=tv[2]; ti[1]=ti[2];
            tv[2]=tv[3]; ti[2]=ti[3];
            tv[3]=tv[4]; ti[3]=ti[4];
            tv[4]=-3e38f; ti[4]=0x7fffffff;
        }
    }

    // cutoff + candidate count (uniform across warp)
    const float cutoff = wv[4] - CUTW;
    int m = 5;
    #pragma unroll
    for (int k = 5; k < 12; k++) m += (wv[k] >= cutoff) ? 1 : 0;

    // exact fp32 refine of candidates (warp-parallel dot per candidate)
    float cv[12];
    #pragma unroll
    for (int j = 0; j < 12; j++) {
        cv[j] = -3e38f;
        if (j < m) {   // m uniform -> convergent
            const int idx = wix[j];
            const float4* bp = (const float4*)(bank + (size_t)idx * DIM + lane * 8);
            const float4 a = __ldg(bp), b = __ldg(bp + 1);
            float d = qn[0] * a.x;
            d = fmaf(qn[1], a.y, d); d = fmaf(qn[2], a.z, d); d = fmaf(qn[3], a.w, d);
            d = fmaf(qn[4], b.x, d); d = fmaf(qn[5], b.y, d);
            d = fmaf(qn[6], b.z, d); d = fmaf(qn[7], b.w, d);
            #pragma unroll
            for (int o = 16; o; o >>= 1) d += __shfl_xor_sync(0xffffffffu, d, o);
            cv[j] = d * g_binv[idx];
        }
    }

    // exact top-5 among candidates (identical computation on all lanes)
    float sv[5]; int si[5];
    unsigned used = 0;
    #pragma unroll
    for (int k = 0; k < 5; k++) {
        float bv = -3e38f; int bi = 0x7fffffff; int bj = 0;
        #pragma unroll
        for (int j = 0; j < 12; j++) {
            const bool ok = (j < m) && !((used >> j) & 1);
            if (ok && (cv[j] > bv || (cv[j] == bv && wix[j] < bi))) {
                bv = cv[j]; bi = wix[j]; bj = j;
            }
        }
        used |= 1u << bj;
        sv[k] = bv; si[k] = bi;
    }

    // softmax
    const float mx = sv[0];
    float e0 = expf(sv[0]-mx), e1 = expf(sv[1]-mx), e2 = expf(sv[2]-mx),
          e3 = expf(sv[3]-mx), e4 = expf(sv[4]-mx);
    const float isum = 1.0f / (e0 + e1 + e2 + e3 + e4);
    const float wgt[5] = {e0*isum, e1*isum, e2*isum, e3*isum, e4*isum};

    // weighted gather: lane covers dims lane*8..+7
    float acc[8] = {0,0,0,0,0,0,0,0};
    #pragma unroll
    for (int k = 0; k < 5; k++) {
        const float4* bp = (const float4*)(bank + (size_t)si[k] * DIM + lane * 8);
        const float4 a = __ldg(bp), b = __ldg(bp + 1);
        acc[0] = fmaf(wgt[k], a.x, acc[0]); acc[1] = fmaf(wgt[k], a.y, acc[1]);
        acc[2] = fmaf(wgt[k], a.z, acc[2]); acc[3] = fmaf(wgt[k], a.w, acc[3]);
        acc[4] = fmaf(wgt[k], b.x, acc[4]); acc[5] = fmaf(wgt[k], b.y, acc[5]);
        acc[6] = fmaf(wgt[k], b.z, acc[6]); acc[7] = fmaf(wgt[k], b.w, acc[7]);
    }
    bf16 n0[8], n1[8];
    #pragma unroll
    for (int i = 0; i < 8; i++) split2(acc[i], n0[i], n1[i]);
    const size_t o = (size_t)r * DIM + lane * 8;
    *(uint4*)(g_nf0 + o) = *(uint4*)n0;
    *(uint4*)(g_nf1 + o) = *(uint4*)n1;
}

// ---------------- MLP kernels: CTA 64 rows x 256 out-cols, warp tile 32x64 ----------------
// per-buf (51200 B): X 2 splits x (64x40 bf16 = 5120) @0 ; W 2 splits x (256x40 bf16 = 20480) @10240
// 2 bufs = 102400 ; Cs overlay 64x264 f32 = 67584 @0
#define MLP_SMEM 102400

template <int NSLAB, int WLD>
__device__ __forceinline__ void mlp_core(
    const bf16* x0a, const bf16* x1a, const bf16* x0b, const bf16* x1b,
    const bf16* w0p, const bf16* w1p, char* sm, u32 sb, int q0)
{
    const int t = threadIdx.x, w = t >> 5;
    const int wy = w >> 2, wx = w & 3;   // 2x4 -> 64 x 256

    FragC c[2][4];
    #pragma unroll
    for (int i = 0; i < 2; i++)
        #pragma unroll
        for (int j = 0; j < 4; j++) wmma::fill_fragment(c[i][j], 0.0f);

    const bf16* wsp[2] = {w0p, w1p};

    auto stage = [&](int kt, int buf) {
        const u32 bb = sb + buf * 51200;
        const bf16* xpp[2];
        xpp[0] = (kt < NSLAB / 2) ? x0a : x0b;
        xpp[1] = (kt < NSLAB / 2) ? x1a : x1b;
        const int xcol = (kt & 7) * 32;
        #pragma unroll
        for (int i = t; i < 2560; i += 256) {
            if (i < 512) {
                const int split = i >> 8, rem = i & 255, row = rem >> 2, seg = rem & 3;
                cp16(bb + split * 5120 + row * 80 + seg * 16,
                     xpp[split] + (size_t)(q0 + row) * DIM + xcol + seg * 8);
            } else {
                const int jj = i - 512;
                const int split = jj >> 10, rem = jj & 1023, row = rem >> 2, seg = rem & 3;
                cp16(bb + 10240 + split * 20480 + row * 80 + seg * 16,
                     wsp[split] + (size_t)row * WLD + kt * 32 + seg * 8);
            }
        }
        cp_commit();
    };

    stage(0, 0);
    #pragma unroll 1
    for (int kt = 0; kt < NSLAB; kt++) {
        const int buf = kt & 1;
        if (kt < NSLAB - 1) { stage(kt + 1, buf ^ 1); cp_wait1(); }
        else cp_wait0();
        __syncthreads();

        const bf16* Xb = (const bf16*)(sm + buf * 51200);
        const bf16* Wb = (const bf16*)(sm + buf * 51200 + 10240);
        #pragma unroll
        for (int kk = 0; kk < 32; kk += 16) {
            FragA a0[2], a1[2];
            #pragma unroll
            for (int i = 0; i < 2; i++) {
                wmma::load_matrix_sync(a0[i], Xb + (wy * 32 + i * 16) * 40 + kk, 40);
                wmma::load_matrix_sync(a1[i], Xb + 2560 + (wy * 32 + i * 16) * 40 + kk, 40);
            }
            #pragma unroll
            for (int sw = 0; sw < 2; sw++) {
                #pragma unroll
                for (int j = 0; j < 4; j++) {
                    FragB b;
                    wmma::load_matrix_sync(b,
                        Wb + sw * 10240 + (wx * 64 + j * 16) * 40 + kk, 40);
                    wmma::mma_sync(c[0][j], a0[0], b, c[0][j]);
                    wmma::mma_sync(c[1][j], a0[1], b, c[1][j]);
                    if (sw == 0) {
                        wmma::mma_sync(c[0][j], a1[0], b, c[0][j]);
                        wmma::mma_sync(c[1][j], a1[1], b, c[1][j]);
                    }
                }
            }
        }
        __syncthreads();
    }

    float* Cs = (float*)sm;
    #pragma unroll
    for (int i = 0; i < 2; i++)
        #pragma unroll
        for (int j = 0; j < 4; j++)
            wmma::store_matrix_sync(Cs + (wy * 32 + i * 16) * 264 + wx * 64 + j * 16,
                                    c[i][j], 264, wmma::mem_row_major);
    __syncthreads();
}

__global__ __launch_bounds__(256, 2) void k_mlp1(const float* __restrict__ b1) {
    extern __shared__ char sm[];
    const u32 sb = smem_u32(sm);
    const int t = threadIdx.x;
    const int q0 = blockIdx.x * 64;
    mlp_core<16, 2 * DIM>(g_f0, g_f1, g_nf0, g_nf1, g_w10, g_w11, sm, sb, q0);

    const float* Cs = (const float*)sm;
    const float bias = __ldg(b1 + t);
    #pragma unroll 2
    for (int r = 0; r < 64; r++) {
        const float v = fmaxf(Cs[r * 264 + t] + bias, 0.0f);
        const size_t o = (size_t)(q0 + r) * DIM + t;
        bf16 h0, h1;
        split2(v, h0, h1);
        g_h0[o] = h0; g_h1[o] = h1;
    }
}

__global__ __launch_bounds__(256, 2) void k_mlp2(const float* __restrict__ b2,
                                                 float* __restrict__ out) {
    extern __shared__ char sm[];
    const u32 sb = smem_u32(sm);
    const int t = threadIdx.x;
    const int q0 = blockIdx.x * 64;
    mlp_core<8, DIM>(g_h0, g_h1, g_h0, g_h1, g_w20, g_w21, sm, sb, q0);

    const float* Cs = (const float*)sm;
    const float bias = __ldg(b2 + t);
    #pragma unroll 2
    for (int r = 0; r < 64; r++)
        out[(size_t)(q0 + r) * DIM + t] = Cs[r * 264 + t] + bias;
}

// ---------------------------------------------------------------------------
extern "C" void kernel_launch(void* const* d_in, const int* in_sizes, int n_in,
                              void* d_out, int out_size) {
    const float* feat = (const float*)d_in[0];
    const float* bank = (const float*)d_in[1];
    const float* W1   = (const float*)d_in[2];
    const float* b1   = (const float*)d_in[3];
    const float* W2   = (const float*)d_in[4];
    const float* b2   = (const float*)d_in[5];
    float* out        = (float*)d_out;

    cudaFuncSetAttribute(k_sims_gemm, cudaFuncAttributeMaxDynamicSharedMemorySize, SIMS_SMEM);
    cudaFuncSetAttribute(k_mlp1, cudaFuncAttributeMaxDynamicSharedMemorySize, MLP_SMEM);
    cudaFuncSetAttribute(k_mlp2, cudaFuncAttributeMaxDynamicSharedMemorySize, MLP_SMEM);

    k_bank_split<<<BANK_P / 8, 256>>>(bank);
    k_feat_split<<<NB / 8, 256>>>(feat);
    k_w_split<<<(DIM * 2 * DIM + 255) / 256, 256>>>(W1, W2);
    k_sims_gemm<<<NB / 64, 256, SIMS_SMEM>>>();
    k_select<<<NB / 8, 256>>>(feat, bank);
    k_mlp1<<<NB / 64, 256, MLP_SMEM>>>(b1);
    k_mlp2<<<NB / 64, 256, MLP_SMEM>>>(b2, out);
}

// round 14
// speedup vs baseline: 1.1399x; 1.1399x over previous
#include <cuda_runtime.h>
#include <cuda_bf16.h>
#include <cuda_fp16.h>
#include <mma.h>
#include <math.h>

using namespace nvcuda;

#define NB      65536
#define DIM     256
#define BANK_N  1000
#define BANK_P  1024
#define CUTW    2.5e-3f

typedef unsigned int       u32;
typedef __nv_bfloat16      bf16;

// ---------------- device scratch (static) ----------------
__device__ __align__(16) bf16  g_bn0[BANK_P * DIM];
__device__ __align__(16) bf16  g_qn0[(size_t)NB * DIM];
__device__ __align__(16) float g_binv[BANK_P];
__device__ __align__(16) float g_qinv[NB];
__device__ __align__(16) __half g_simh[(size_t)NB * BANK_P];   // 134 MB
__device__ __align__(16) bf16  g_f0[(size_t)NB * DIM];
__device__ __align__(16) bf16  g_f1[(size_t)NB * DIM];
__device__ __align__(16) bf16  g_nf0[(size_t)NB * DIM];
__device__ __align__(16) bf16  g_nf1[(size_t)NB * DIM];
__device__ __align__(16) bf16  g_h0[(size_t)NB * DIM];
__device__ __align__(16) bf16  g_h1[(size_t)NB * DIM];
__device__ __align__(16) bf16  g_w10[DIM * 2 * DIM];
__device__ __align__(16) bf16  g_w11[DIM * 2 * DIM];
__device__ __align__(16) bf16  g_w20[DIM * DIM];
__device__ __align__(16) bf16  g_w21[DIM * DIM];

// ---------------- helpers ----------------
__device__ __forceinline__ u32 smem_u32(const void* p) {
    u32 a;
    asm("{ .reg .u64 t; cvta.to.shared.u64 t, %1; cvt.u32.u64 %0, t; }" : "=r"(a) : "l"(p));
    return a;
}
__device__ __forceinline__ void cp16(u32 dst, const void* src) {
    asm volatile("cp.async.cg.shared.global [%0], [%1], 16;" :: "r"(dst), "l"(src));
}
__device__ __forceinline__ void cp_commit() { asm volatile("cp.async.commit_group;" ::: "memory"); }
__device__ __forceinline__ void cp_wait0()  { asm volatile("cp.async.wait_group 0;" ::: "memory"); }
__device__ __forceinline__ void cp_wait1()  { asm volatile("cp.async.wait_group 1;" ::: "memory"); }

__device__ __forceinline__ void ldsm_x4(u32& r0, u32& r1, u32& r2, u32& r3, u32 addr) {
    asm volatile("ldmatrix.sync.aligned.m8n8.x4.shared.b16 {%0,%1,%2,%3}, [%4];"
                 : "=r"(r0), "=r"(r1), "=r"(r2), "=r"(r3) : "r"(addr));
}
__device__ __forceinline__ void mma16816(float* c, const u32* a, u32 b0, u32 b1) {
    asm volatile(
        "mma.sync.aligned.m16n8k16.row.col.f32.bf16.bf16.f32 "
        "{%0,%1,%2,%3}, {%4,%5,%6,%7}, {%8,%9}, {%0,%1,%2,%3};"
        : "+f"(c[0]), "+f"(c[1]), "+f"(c[2]), "+f"(c[3])
        : "r"(a[0]), "r"(a[1]), "r"(a[2]), "r"(a[3]), "r"(b0), "r"(b1));
}

__device__ __forceinline__ u32 redux_max_u32(u32 v) {
    u32 r;
    asm("redux.sync.max.u32 %0, %1, 0xffffffff;" : "=r"(r) : "r"(v));
    return r;
}
__device__ __forceinline__ u32 redux_min_u32(u32 v) {
    u32 r;
    asm("redux.sync.min.u32 %0, %1, 0xffffffff;" : "=r"(r) : "r"(v));
    return r;
}
__device__ __forceinline__ u32 ford(float f) {
    u32 u = __float_as_uint(f);
    return (u & 0x80000000u) ? ~u : (u | 0x80000000u);
}
__device__ __forceinline__ float funord(u32 k) {
    u32 u = (k & 0x80000000u) ? (k ^ 0x80000000u) : ~k;
    return __uint_as_float(u);
}

typedef wmma::fragment<wmma::matrix_a, 16, 16, 16, bf16, wmma::row_major> FragA;
typedef wmma::fragment<wmma::matrix_b, 16, 16, 16, bf16, wmma::col_major> FragB;
typedef wmma::fragment<wmma::accumulator, 16, 16, 16, float> FragC;

__device__ __forceinline__ float warp_row_sumsq(float4 v0, float4 v1) {
    float s = v0.x*v0.x + v0.y*v0.y + v0.z*v0.z + v0.w*v0.w
            + v1.x*v1.x + v1.y*v1.y + v1.z*v1.z + v1.w*v1.w;
    #pragma unroll
    for (int o = 16; o; o >>= 1) s += __shfl_xor_sync(0xffffffffu, s, o);
    return s;
}
__device__ __forceinline__ void split2(float x, bf16& a, bf16& b) {
    a = __float2bfloat16(x);
    b = __float2bfloat16(x - __bfloat162float(a));
}

// ---------------- split kernels ----------------
__global__ void k_bank_split(const float* __restrict__ bank) {
    const int w = threadIdx.x >> 5, l = threadIdx.x & 31;
    const int r = blockIdx.x * 8 + w;
    float4 v0 = make_float4(0,0,0,0), v1 = v0;
    if (r < BANK_N) {
        const float* src = bank + (size_t)r * DIM + l * 8;
        v0 = *(const float4*)src; v1 = *(const float4*)(src + 4);
    }
    const float s = warp_row_sumsq(v0, v1);
    const float inv = 1.0f / fmaxf(sqrtf(s), 1e-12f);
    float xv[8] = {v0.x, v0.y, v0.z, v0.w, v1.x, v1.y, v1.z, v1.w};
    bf16 o0[8];
    #pragma unroll
    for (int i = 0; i < 8; i++)
        o0[i] = __float2bfloat16((r < BANK_N) ? xv[i] * inv : 0.0f);
    *(uint4*)(g_bn0 + (size_t)r * DIM + l * 8) = *(uint4*)o0;
    if (l == 0) g_binv[r] = (r < BANK_N) ? inv : 0.0f;
}

__global__ void k_feat_split(const float* __restrict__ feat) {
    const int w = threadIdx.x >> 5, l = threadIdx.x & 31;
    const int r = blockIdx.x * 8 + w;
    const float* src = feat + (size_t)r * DIM + l * 8;
    float4 v0 = *(const float4*)src;
    float4 v1 = *(const float4*)(src + 4);
    const float s = warp_row_sumsq(v0, v1);
    const float inv = 1.0f / fmaxf(sqrtf(s), 1e-12f);
    float xv[8] = {v0.x, v0.y, v0.z, v0.w, v1.x, v1.y, v1.z, v1.w};
    bf16 q0[8], f0[8], f1[8];
    #pragma unroll
    for (int i = 0; i < 8; i++) {
        q0[i] = __float2bfloat16(xv[i] * inv);
        split2(xv[i], f0[i], f1[i]);
    }
    const size_t o = (size_t)r * DIM + l * 8;
    *(uint4*)(g_qn0 + o) = *(uint4*)q0;
    *(uint4*)(g_f0 + o)  = *(uint4*)f0;
    *(uint4*)(g_f1 + o)  = *(uint4*)f1;
    if (l == 0) g_qinv[r] = inv;
}

__global__ void k_w_split(const float* __restrict__ W1, const float* __restrict__ W2) {
    const int i = blockIdx.x * 256 + threadIdx.x;
    if (i < DIM * 2 * DIM) split2(W1[i], g_w10[i], g_w11[i]);
    if (i < DIM * DIM)     split2(W2[i], g_w20[i], g_w21[i]);
}

// ---------------- k_sims_gemm: mma.sync bf16 GEMM -> g_simh (fp16, direct reg stores) ----------------
// smem: As @0 (64x264 bf16 = 33792) ; Bbuf @33792 2 x (256x72 bf16 = 36864)
#define S_AS 0
#define S_BB 33792
#define SIMS_SMEM 107520

__global__ __launch_bounds__(256, 2) void k_sims_gemm() {
    extern __shared__ char sm[];
    bf16* As = (bf16*)(sm + S_AS);
    const u32 sb = smem_u32(sm);
    const int t = threadIdx.x, w = t >> 5, lane = t & 31;
    const int wy = w >> 2, wx = w & 3;          // 2x4 warps -> CTA tile 64 x 256
    const int q0 = blockIdx.x * 64;
    const int g = lane >> 2, tig = lane & 3;

    // prologue: stage B(nt0,kt0) into buf0 (async), then A resident
    #pragma unroll
    for (int i = t; i < 2048; i += 256) {
        const int c = i >> 3, seg = i & 7;
        cp16(sb + S_BB + c * 144 + seg * 16, g_bn0 + (size_t)c * DIM + seg * 8);
    }
    cp_commit();
    #pragma unroll
    for (int i = t; i < 2048; i += 256) {
        const int row = i >> 5, seg = i & 31;
        *(uint4*)(As + row * 264 + seg * 8) =
            *(const uint4*)(g_qn0 + (size_t)(q0 + row) * DIM + seg * 8);
    }

    // ldmatrix lane addressing: matrix = lane>>3; row-in-matrix = lane&7
    const int lrow = (lane & 7) + ((lane >> 3) & 1) * 8;  // +8 for odd matrices (row/n half)
    const int lkof = ((lane >> 4) & 1) * 8;               // +8 k for matrices 2,3
    u32 aAddr[2], bAddr[4];
    #pragma unroll
    for (int i = 0; i < 2; i++)
        aAddr[i] = sb + S_AS + ((wy * 32 + i * 16 + lrow) * 264 + lkof) * 2;
    #pragma unroll
    for (int p = 0; p < 4; p++)
        bAddr[p] = sb + S_BB + ((wx * 64 + p * 16 + lrow) * 72 + lkof) * 2;

    #pragma unroll 1
    for (int nt = 0; nt < 4; nt++) {
        float c[2][8][4];
        #pragma unroll
        for (int i = 0; i < 2; i++)
            #pragma unroll
            for (int j = 0; j < 8; j++)
                #pragma unroll
                for (int e = 0; e < 4; e++) c[i][j][e] = 0.0f;

        #pragma unroll 1
        for (int kt = 0; kt < 4; kt++) {
            const int buf = kt & 1;
            if (kt < 3) {
                const u32 db = sb + S_BB + (buf ^ 1) * 36864;
                #pragma unroll
                for (int i = t; i < 2048; i += 256) {
                    const int cc = i >> 3, seg = i & 7;
                    cp16(db + cc * 144 + seg * 16,
                         g_bn0 + (size_t)(nt * 256 + cc) * DIM + (kt + 1) * 64 + seg * 8);
                }
                cp_commit();
                cp_wait1();
            } else {
                cp_wait0();
            }
            __syncthreads();

            const u32 bufOfs = buf * 36864;
            #pragma unroll
            for (int kk = 0; kk < 4; kk++) {
                u32 a[2][4];
                #pragma unroll
                for (int i = 0; i < 2; i++)
                    ldsm_x4(a[i][0], a[i][1], a[i][2], a[i][3],
                            aAddr[i] + (kt * 64 + kk * 16) * 2);
                #pragma unroll
                for (int p = 0; p < 4; p++) {
                    u32 b0, b1, b2, b3;   // b0/b1: frag-b0 of n-tiles 2p,2p+1; b2/b3: frag-b1
                    ldsm_x4(b0, b1, b2, b3, bAddr[p] + bufOfs + (kk * 16) * 2);
                    #pragma unroll
                    for (int i = 0; i < 2; i++) {
                        mma16816(c[i][2 * p],     a[i], b0, b2);
                        mma16816(c[i][2 * p + 1], a[i], b1, b3);
                    }
                }
            }
            __syncthreads();
        }

        // overlap: prestage next chunk's kt0 into buf0
        if (nt < 3) {
            #pragma unroll
            for (int i = t; i < 2048; i += 256) {
                const int cc = i >> 3, seg = i & 7;
                cp16(sb + S_BB + cc * 144 + seg * 16,
                     g_bn0 + (size_t)((nt + 1) * 256 + cc) * DIM + seg * 8);
            }
            cp_commit();
        }

        // direct half2 stores: c0,c1 -> (row g), c2,c3 -> (row g+8), col = 2*tig
        #pragma unroll
        for (int i = 0; i < 2; i++) {
            const size_t row0 = (size_t)(q0 + wy * 32 + i * 16 + g);
            #pragma unroll
            for (int j = 0; j < 8; j++) {
                const int col = nt * 256 + wx * 64 + j * 8 + 2 * tig;
                *(__half2*)(g_simh + row0 * BANK_P + col) =
                    __floats2half2_rn(c[i][j][0], c[i][j][1]);
                *(__half2*)(g_simh + (row0 + 8) * BANK_P + col) =
                    __floats2half2_rn(c[i][j][2], c[i][j][3]);
            }
        }
    }
}

// ---------------- k_select: warp per row; fp16 scan + redux merge + exact refine + gather ----------------
__global__ __launch_bounds__(256) void k_select(const float* __restrict__ feat,
                                               const float* __restrict__ bank) {
    const int t = threadIdx.x, wid = t >> 5, lane = t & 31;
    const int r = blockIdx.x * 8 + wid;

    // exact qn slice for this lane (dims lane*8 .. lane*8+7)
    const float qinv = g_qinv[r];
    float qn[8];
    {
        const float4* fp = (const float4*)(feat + (size_t)r * DIM + lane * 8);
        float4 a = __ldg(fp), b = __ldg(fp + 1);
        qn[0] = a.x * qinv; qn[1] = a.y * qinv; qn[2] = a.z * qinv; qn[3] = a.w * qinv;
        qn[4] = b.x * qinv; qn[5] = b.y * qinv; qn[6] = b.z * qinv; qn[7] = b.w * qinv;
    }

    // lane-local top-5 over 32 values (16 half2 steps, coalesced 128B)
    float tv[5]; int ti[5];
    #pragma unroll
    for (int i = 0; i < 5; i++) { tv[i] = -3e38f; ti[i] = 0x7fffffff; }
    const __half2* srow = (const __half2*)(g_simh + (size_t)r * BANK_P);
    #pragma unroll 4
    for (int j = 0; j < 16; j++) {
        const int p = j * 32 + lane;           // half2 index; cols 2p, 2p+1
        const __half2 h = __ldg(srow + p);
        float2 v = __half22float2(h);
        const int idx0 = 2 * p, idx1 = 2 * p + 1;
        if (idx0 >= BANK_N) v.x = -3e38f;
        if (idx1 >= BANK_N) v.y = -3e38f;
        if (v.x > tv[4]) {
            tv[4] = v.x; ti[4] = idx0;
            if (tv[4] > tv[3]) { float a=tv[4];tv[4]=tv[3];tv[3]=a; int b=ti[4];ti[4]=ti[3];ti[3]=b; }
            if (tv[3] > tv[2]) { float a=tv[3];tv[3]=tv[2];tv[2]=a; int b=ti[3];ti[3]=ti[2];ti[2]=b; }
            if (tv[2] > tv[1]) { float a=tv[2];tv[2]=tv[1];tv[1]=a; int b=ti[2];ti[2]=ti[1];ti[1]=b; }
            if (tv[1] > tv[0]) { float a=tv[1];tv[1]=tv[0];tv[0]=a; int b=ti[1];ti[1]=ti[0];ti[0]=b; }
        }
        if (v.y > tv[4]) {
            tv[4] = v.y; ti[4] = idx1;
            if (tv[4] > tv[3]) { float a=tv[4];tv[4]=tv[3];tv[3]=a; int b=ti[4];ti[4]=ti[3];ti[3]=b; }
            if (tv[3] > tv[2]) { float a=tv[3];tv[3]=tv[2];tv[2]=a; int b=ti[3];ti[3]=ti[2];ti[2]=b; }
            if (tv[2] > tv[1]) { float a=tv[2];tv[2]=tv[1];tv[1]=a; int b=ti[2];ti[2]=ti[1];ti[1]=b; }
            if (tv[1] > tv[0]) { float a=tv[1];tv[1]=tv[0];tv[0]=a; int b=ti[1];ti[1]=ti[0];ti[0]=b; }
        }
    }

    // warp merge via redux: extract row top-12 (descending, tie -> lower idx)
    float wv[12]; int wix[12];
    #pragma unroll
    for (int k = 0; k < 12; k++) {
        const u32 key = ford(tv[0]);
        const u32 mx = redux_max_u32(key);
        const bool has = (key == mx);
        const u32 cand = has ? (u32)ti[0] : 0xffffffffu;
        const u32 mi = redux_min_u32(cand);
        wv[k] = funord(mx);
        wix[k] = (int)mi;
        if (has && (u32)ti[0] == mi) {   // winner lane: shift list down
            tv[0]=tv[1]; ti[0]=ti[1];
            tv[1]=tv[2]; ti[1]=ti[2];
            tv[2]=tv[3]; ti[2]=ti[3];
            tv[3]=tv[4]; ti[3]=ti[4];
            tv[4]=-3e38f; ti[4]=0x7fffffff;
        }
    }

    // cutoff + candidate count (uniform across warp)
    const float cutoff = wv[4] - CUTW;
    int m = 5;
    #pragma unroll
    for (int k = 5; k < 12; k++) m += (wv[k] >= cutoff) ? 1 : 0;

    // exact fp32 refine of candidates (warp-parallel dot per candidate)
    float cv[12];
    #pragma unroll
    for (int j = 0; j < 12; j++) {
        cv[j] = -3e38f;
        if (j < m) {   // m uniform -> convergent
            const int idx = wix[j];
            const float4* bp = (const float4*)(bank + (size_t)idx * DIM + lane * 8);
            const float4 a = __ldg(bp), b = __ldg(bp + 1);
            float d = qn[0] * a.x;
            d = fmaf(qn[1], a.y, d); d = fmaf(qn[2], a.z, d); d = fmaf(qn[3], a.w, d);
            d = fmaf(qn[4], b.x, d); d = fmaf(qn[5], b.y, d);
            d = fmaf(qn[6], b.z, d); d = fmaf(qn[7], b.w, d);
            #pragma unroll
            for (int o = 16; o; o >>= 1) d += __shfl_xor_sync(0xffffffffu, d, o);
            cv[j] = d * g_binv[idx];
        }
    }

    // exact top-5 among candidates (identical computation on all lanes)
    float sv[5]; int si[5];
    unsigned used = 0;
    #pragma unroll
    for (int k = 0; k < 5; k++) {
        float bv = -3e38f; int bi = 0x7fffffff; int bj = 0;
        #pragma unroll
        for (int j = 0; j < 12; j++) {
            const bool ok = (j < m) && !((used >> j) & 1);
            if (ok && (cv[j] > bv || (cv[j] == bv && wix[j] < bi))) {
                bv = cv[j]; bi = wix[j]; bj = j;
            }
        }
        used |= 1u << bj;
        sv[k] = bv; si[k] = bi;
    }

    // softmax
    const float mx = sv[0];
    float e0 = expf(sv[0]-mx), e1 = expf(sv[1]-mx), e2 = expf(sv[2]-mx),
          e3 = expf(sv[3]-mx), e4 = expf(sv[4]-mx);
    const float isum = 1.0f / (e0 + e1 + e2 + e3 + e4);
    const float wgt[5] = {e0*isum, e1*isum, e2*isum, e3*isum, e4*isum};

    // weighted gather: lane covers dims lane*8..+7
    float acc[8] = {0,0,0,0,0,0,0,0};
    #pragma unroll
    for (int k = 0; k < 5; k++) {
        const float4* bp = (const float4*)(bank + (size_t)si[k] * DIM + lane * 8);
        const float4 a = __ldg(bp), b = __ldg(bp + 1);
        acc[0] = fmaf(wgt[k], a.x, acc[0]); acc[1] = fmaf(wgt[k], a.y, acc[1]);
        acc[2] = fmaf(wgt[k], a.z, acc[2]); acc[3] = fmaf(wgt[k], a.w, acc[3]);
        acc[4] = fmaf(wgt[k], b.x, acc[4]); acc[5] = fmaf(wgt[k], b.y, acc[5]);
        acc[6] = fmaf(wgt[k], b.z, acc[6]); acc[7] = fmaf(wgt[k], b.w, acc[7]);
    }
    bf16 n0[8], n1[8];
    #pragma unroll
    for (int i = 0; i < 8; i++) split2(acc[i], n0[i], n1[i]);
    const size_t o = (size_t)r * DIM + lane * 8;
    *(uint4*)(g_nf0 + o) = *(uint4*)n0;
    *(uint4*)(g_nf1 + o) = *(uint4*)n1;
}

// ---------------- MLP kernels: CTA 64 rows x 256 out-cols, warp tile 32x64 ----------------
// per-buf (51200 B): X 2 splits x (64x40 bf16 = 5120) @0 ; W 2 splits x (256x40 bf16 = 20480) @10240
// 2 bufs = 102400 ; Cs overlay 64x264 f32 = 67584 @0
#define MLP_SMEM 102400

template <int NSLAB, int WLD>
__device__ __forceinline__ void mlp_core(
    const bf16* x0a, const bf16* x1a, const bf16* x0b, const bf16* x1b,
    const bf16* w0p, const bf16* w1p, char* sm, u32 sb, int q0)
{
    const int t = threadIdx.x, w = t >> 5;
    const int wy = w >> 2, wx = w & 3;   // 2x4 -> 64 x 256

    FragC c[2][4];
    #pragma unroll
    for (int i = 0; i < 2; i++)
        #pragma unroll
        for (int j = 0; j < 4; j++) wmma::fill_fragment(c[i][j], 0.0f);

    const bf16* wsp[2] = {w0p, w1p};

    auto stage = [&](int kt, int buf) {
        const u32 bb = sb + buf * 51200;
        const bf16* xpp[2];
        xpp[0] = (kt < NSLAB / 2) ? x0a : x0b;
        xpp[1] = (kt < NSLAB / 2) ? x1a : x1b;
        const int xcol = (kt & 7) * 32;
        #pragma unroll
        for (int i = t; i < 2560; i += 256) {
            if (i < 512) {
                const int split = i >> 8, rem = i & 255, row = rem >> 2, seg = rem & 3;
                cp16(bb + split * 5120 + row * 80 + seg * 16,
                     xpp[split] + (size_t)(q0 + row) * DIM + xcol + seg * 8);
            } else {
                const int jj = i - 512;
                const int split = jj >> 10, rem = jj & 1023, row = rem >> 2, seg = rem & 3;
                cp16(bb + 10240 + split * 20480 + row * 80 + seg * 16,
                     wsp[split] + (size_t)row * WLD + kt * 32 + seg * 8);
            }
        }
        cp_commit();
    };

    stage(0, 0);
    #pragma unroll 1
    for (int kt = 0; kt < NSLAB; kt++) {
        const int buf = kt & 1;
        if (kt < NSLAB - 1) { stage(kt + 1, buf ^ 1); cp_wait1(); }
        else cp_wait0();
        __syncthreads();

        const bf16* Xb = (const bf16*)(sm + buf * 51200);
        const bf16* Wb = (const bf16*)(sm + buf * 51200 + 10240);
        #pragma unroll
        for (int kk = 0; kk < 32; kk += 16) {
            FragA a0[2], a1[2];
            #pragma unroll
            for (int i = 0; i < 2; i++) {
                wmma::load_matrix_sync(a0[i], Xb + (wy * 32 + i * 16) * 40 + kk, 40);
                wmma::load_matrix_sync(a1[i], Xb + 2560 + (wy * 32 + i * 16) * 40 + kk, 40);
            }
            #pragma unroll
            for (int sw = 0; sw < 2; sw++) {
                #pragma unroll
                for (int j = 0; j < 4; j++) {
                    FragB b;
                    wmma::load_matrix_sync(b,
                        Wb + sw * 10240 + (wx * 64 + j * 16) * 40 + kk, 40);
                    wmma::mma_sync(c[0][j], a0[0], b, c[0][j]);
                    wmma::mma_sync(c[1][j], a0[1], b, c[1][j]);
                    if (sw == 0) {
                        wmma::mma_sync(c[0][j], a1[0], b, c[0][j]);
                        wmma::mma_sync(c[1][j], a1[1], b, c[1][j]);
                    }
                }
            }
        }
        __syncthreads();
    }

    float* Cs = (float*)sm;
    #pragma unroll
    for (int i = 0; i < 2; i++)
        #pragma unroll
        for (int j = 0; j < 4; j++)
            wmma::store_matrix_sync(Cs + (wy * 32 + i * 16) * 264 + wx * 64 + j * 16,
                                    c[i][j], 264, wmma::mem_row_major);
    __syncthreads();
}

__global__ __launch_bounds__(256, 2) void k_mlp1(const float* __restrict__ b1) {
    extern __shared__ char sm[];
    const u32 sb = smem_u32(sm);
    const int t = threadIdx.x;
    const int q0 = blockIdx.x * 64;
    mlp_core<16, 2 * DIM>(g_f0, g_f1, g_nf0, g_nf1, g_w10, g_w11, sm, sb, q0);

    const float* Cs = (const float*)sm;
    const float bias = __ldg(b1 + t);
    #pragma unroll 2
    for (int r = 0; r < 64; r++) {
        const float v = fmaxf(Cs[r * 264 + t] + bias, 0.0f);
        const size_t o = (size_t)(q0 + r) * DIM + t;
        bf16 h0, h1;
        split2(v, h0, h1);
        g_h0[o] = h0; g_h1[o] = h1;
    }
}

__global__ __launch_bounds__(256, 2) void k_mlp2(const float* __restrict__ b2,
                                                 float* __restrict__ out) {
    extern __shared__ char sm[];
    const u32 sb = smem_u32(sm);
    const int t = threadIdx.x;
    const int q0 = blockIdx.x * 64;
    mlp_core<8, DIM>(g_h0, g_h1, g_h0, g_h1, g_w20, g_w21, sm, sb, q0);

    const float* Cs = (const float*)sm;
    const float bias = __ldg(b2 + t);
    #pragma unroll 2
    for (int r = 0; r < 64; r++)
        out[(size_t)(q0 + r) * DIM + t] = Cs[r * 264 + t] + bias;
}

// ---------------------------------------------------------------------------
extern "C" void kernel_launch(void* const* d_in, const int* in_sizes, int n_in,
                              void* d_out, int out_size) {
    const float* feat = (const float*)d_in[0];
    const float* bank = (const float*)d_in[1];
    const float* W1   = (const float*)d_in[2];
    const float* b1   = (const float*)d_in[3];
    const float* W2   = (const float*)d_in[4];
    const float* b2   = (const float*)d_in[5];
    float* out        = (float*)d_out;

    cudaFuncSetAttribute(k_sims_gemm, cudaFuncAttributeMaxDynamicSharedMemorySize, SIMS_SMEM);
    cudaFuncSetAttribute(k_mlp1, cudaFuncAttributeMaxDynamicSharedMemorySize, MLP_SMEM);
    cudaFuncSetAttribute(k_mlp2, cudaFuncAttributeMaxDynamicSharedMemorySize, MLP_SMEM);

    k_bank_split<<<BANK_P / 8, 256>>>(bank);
    k_feat_split<<<NB / 8, 256>>>(feat);
    k_w_split<<<(DIM * 2 * DIM + 255) / 256, 256>>>(W1, W2);
    k_sims_gemm<<<NB / 64, 256, SIMS_SMEM>>>();
    k_select<<<NB / 8, 256>>>(feat, bank);
    k_mlp1<<<NB / 64, 256, MLP_SMEM>>>(b1);
    k_mlp2<<<NB / 64, 256, MLP_SMEM>>>(b2, out);
}